// round 13
// baseline (speedup 1.0000x reference)
#include <cuda_runtime.h>
#include <cstdint>

// N=100000 candidates, OBS=16, FEAT=96 -> ROW=1536 floats per candidate.
// target_vels row = 25*96 = 2400 floats.
#define ROW_F       1536
#define ROW_F4      (ROW_F / 4)       // 384 float4
#define ROW_F8      (ROW_F / 8)       // 192 x 32B chunks
#define F8_PER_LANE (ROW_F8 / 32)     // 6 iterations per warp
#define OUT_F       2400
#define OUT_F4      (OUT_F / 4)       // 600
#define WARPS_PER_BLOCK 8

// Statically initialized for the first (uncaptured) correctness call; the
// gather kernel (last in dependency order) resets it after use, so every
// graph replay starts clean.
__device__ unsigned long long g_best = 0xFFFFFFFFFFFFFFFFULL;

// 256-bit global loads (sm_100+): 6 LDG.256 per row instead of 12 LDG.128 —
// half the LSU issue slots and L1tex wavefront-queue entries per byte.
// 6 blocks/SM (75% occ) leaves register headroom for the 16-float live set.
__global__ __launch_bounds__(256, 6) void nn_dist_kernel(
    const float* __restrict__ in_pose,
    const float* __restrict__ train,
    int N)
{
    __shared__ float4 s_q[ROW_F4];
    __shared__ unsigned long long s_best[WARPS_PER_BLOCK];

    const int tid  = threadIdx.x;
    const int warp = tid >> 5;
    const int lane = tid & 31;

    // stage query (6 KB) into shared
    for (int i = tid; i < ROW_F4; i += blockDim.x)
        s_q[i] = reinterpret_cast<const float4*>(in_pose)[i];
    __syncthreads();

    const int cand = blockIdx.x * WARPS_PER_BLOCK + warp;
    unsigned long long packed = 0xFFFFFFFFFFFFFFFFULL;

    if (cand < N) {
        const float* row = train + (size_t)cand * ROW_F;
        float acc = 0.f;
        #pragma unroll
        for (int j = 0; j < F8_PER_LANE; j++) {
            const int idx = j * 32 + lane;          // 32B-chunk index in row
            float a0, a1, a2, a3, a4, a5, a6, a7;
            asm volatile(
                "ld.global.nc.v8.f32 {%0,%1,%2,%3,%4,%5,%6,%7}, [%8];"
                : "=f"(a0), "=f"(a1), "=f"(a2), "=f"(a3),
                  "=f"(a4), "=f"(a5), "=f"(a6), "=f"(a7)
                : "l"(row + (size_t)idx * 8));
            float4 q0 = s_q[2 * idx];
            float4 q1 = s_q[2 * idx + 1];
            float d0 = a0 - q0.x, d1 = a1 - q0.y, d2 = a2 - q0.z, d3 = a3 - q0.w;
            float d4 = a4 - q1.x, d5 = a5 - q1.y, d6 = a6 - q1.z, d7 = a7 - q1.w;
            acc += d0 * d0 + d1 * d1 + d2 * d2 + d3 * d3
                 + d4 * d4 + d5 * d5 + d6 * d6 + d7 * d7;
        }
        #pragma unroll
        for (int o = 16; o > 0; o >>= 1)
            acc += __shfl_xor_sync(0xFFFFFFFFu, acc, o);
        // acc >= 0 -> IEEE bits order-preserving; low 32 = index, so u64 min
        // ties break to the SMALLEST index (jnp.argmin first-min semantics).
        packed = ((unsigned long long)__float_as_uint(acc) << 32) | (unsigned)cand;
    }

    if (lane == 0) s_best[warp] = packed;
    __syncthreads();

    if (tid == 0) {
        unsigned long long b = s_best[0];
        #pragma unroll
        for (int w = 1; w < WARPS_PER_BLOCK; w++) b = min(b, s_best[w]);
        atomicMin(&g_best, b);
    }
    // Signal PDL: this block's contribution to g_best is committed.
    cudaTriggerProgrammaticLaunchCompletion();
}

// Launched with programmatic dependency: resident during the dist kernel,
// proceeds the instant all dist blocks have triggered (atomicMins visible).
__global__ void nn_gather_kernel(const float* __restrict__ target_vels,
                                 float* __restrict__ out)
{
    cudaGridDependencySynchronize();

    __shared__ unsigned int s_bestidx;
    if (threadIdx.x == 0)
        s_bestidx = (unsigned)(g_best & 0xFFFFFFFFULL);
    __syncthreads();

    const float4* src = reinterpret_cast<const float4*>(target_vels)
                        + (size_t)s_bestidx * OUT_F4;
    float4* dst = reinterpret_cast<float4*>(out);
    for (int i = threadIdx.x; i < OUT_F4; i += blockDim.x)
        dst[i] = src[i];

    __syncthreads();
    if (threadIdx.x == 0)
        g_best = 0xFFFFFFFFFFFFFFFFULL;   // clean state for next replay
}

extern "C" void kernel_launch(void* const* d_in, const int* in_sizes, int n_in,
                              void* d_out, int out_size)
{
    const float* in_pose     = (const float*)d_in[0];   // [16, 96]
    const float* train_poses = (const float*)d_in[1];   // [N, 16, 96]
    const float* target_vels = (const float*)d_in[2];   // [N, 25, 96]
    float* out = (float*)d_out;                          // [25, 96]

    const int N = in_sizes[1] / ROW_F;
    const int blocks = (N + WARPS_PER_BLOCK - 1) / WARPS_PER_BLOCK;

    nn_dist_kernel<<<blocks, 256>>>(in_pose, train_poses, N);

    // Gather with programmatic dependent launch: overlaps launch/prologue
    // with the dist kernel; self-synchronizes via gridDependencySynchronize.
    cudaLaunchAttribute attrs[1];
    attrs[0].id = cudaLaunchAttributeProgrammaticStreamSerialization;
    attrs[0].val.programmaticStreamSerializationAllowed = 1;

    cudaLaunchConfig_t cfg = {};
    cfg.gridDim  = dim3(1, 1, 1);
    cfg.blockDim = dim3(256, 1, 1);
    cfg.dynamicSmemBytes = 0;
    cfg.stream = 0;
    cfg.attrs = attrs;
    cfg.numAttrs = 1;

    cudaLaunchKernelEx(&cfg, nn_gather_kernel, target_vels, out);
}

// round 14
// speedup vs baseline: 1.0180x; 1.0180x over previous
#include <cuda_runtime.h>
#include <cstdint>

// N=100000 candidates, OBS=16, FEAT=96 -> ROW=1536 floats per candidate.
// target_vels row = 25*96 = 2400 floats.
#define ROW_F       1536
#define ROW_F4      (ROW_F / 4)       // 384 float4
#define F4_PER_LANE (ROW_F4 / 32)     // 12
#define OUT_F       2400
#define OUT_F4      (OUT_F / 4)       // 600
#define WARPS_PER_BLOCK 8

// Statically initialized for the first (uncaptured) correctness call; the
// gather kernel (last in dependency order) resets it after use, so every
// graph replay starts clean.
__device__ unsigned long long g_best = 0xFFFFFFFFFFFFFFFFULL;

// Floor configuration (best measured: 90.62us). One warp per candidate,
// 8 warps/block, shared-staged query (LDS rides the smem port -> exactly one
// LDG per loop iteration), 32 regs, ~97% occupancy. The 614 MB train stream
// runs at ~6.9 TB/s (~87% of HBM spec) — the hardware read ceiling for this
// pattern. Verified-neutral alternatives: LDG.256, __ldcs, 2 cands/warp,
// persistent grid, 128-thr blocks, global-resident query. Traffic is
// irreducible for an exact argmin.
__global__ __launch_bounds__(256, 8) void nn_dist_kernel(
    const float* __restrict__ in_pose,
    const float* __restrict__ train,
    int N)
{
    __shared__ float4 s_q[ROW_F4];
    __shared__ unsigned long long s_best[WARPS_PER_BLOCK];

    const int tid  = threadIdx.x;
    const int warp = tid >> 5;
    const int lane = tid & 31;

    // stage query (6 KB) into shared
    for (int i = tid; i < ROW_F4; i += blockDim.x)
        s_q[i] = reinterpret_cast<const float4*>(in_pose)[i];
    __syncthreads();

    const int cand = blockIdx.x * WARPS_PER_BLOCK + warp;
    unsigned long long packed = 0xFFFFFFFFFFFFFFFFULL;

    if (cand < N) {
        const float4* row = reinterpret_cast<const float4*>(train) + (size_t)cand * ROW_F4;
        float acc = 0.f;
        #pragma unroll
        for (int j = 0; j < F4_PER_LANE; j++) {
            const int idx = j * 32 + lane;
            float4 a = row[idx];
            float4 q = s_q[idx];
            float dx = a.x - q.x;
            float dy = a.y - q.y;
            float dz = a.z - q.z;
            float dw = a.w - q.w;
            acc += dx * dx + dy * dy + dz * dz + dw * dw;
        }
        #pragma unroll
        for (int o = 16; o > 0; o >>= 1)
            acc += __shfl_xor_sync(0xFFFFFFFFu, acc, o);
        // acc >= 0 -> IEEE bits order-preserving; low 32 = index, so u64 min
        // ties break to the SMALLEST index (jnp.argmin first-min semantics).
        packed = ((unsigned long long)__float_as_uint(acc) << 32) | (unsigned)cand;
    }

    if (lane == 0) s_best[warp] = packed;
    __syncthreads();

    if (tid == 0) {
        unsigned long long b = s_best[0];
        #pragma unroll
        for (int w = 1; w < WARPS_PER_BLOCK; w++) b = min(b, s_best[w]);
        atomicMin(&g_best, b);
    }
    // Signal PDL: this block's contribution to g_best is committed.
    cudaTriggerProgrammaticLaunchCompletion();
}

// Launched with programmatic dependency: resident during the dist kernel,
// proceeds the instant all dist blocks have triggered (atomicMins visible).
__global__ void nn_gather_kernel(const float* __restrict__ target_vels,
                                 float* __restrict__ out)
{
    cudaGridDependencySynchronize();

    __shared__ unsigned int s_bestidx;
    if (threadIdx.x == 0)
        s_bestidx = (unsigned)(g_best & 0xFFFFFFFFULL);
    __syncthreads();

    const float4* src = reinterpret_cast<const float4*>(target_vels)
                        + (size_t)s_bestidx * OUT_F4;
    float4* dst = reinterpret_cast<float4*>(out);
    for (int i = threadIdx.x; i < OUT_F4; i += blockDim.x)
        dst[i] = src[i];

    __syncthreads();
    if (threadIdx.x == 0)
        g_best = 0xFFFFFFFFFFFFFFFFULL;   // clean state for next replay
}

extern "C" void kernel_launch(void* const* d_in, const int* in_sizes, int n_in,
                              void* d_out, int out_size)
{
    const float* in_pose     = (const float*)d_in[0];   // [16, 96]
    const float* train_poses = (const float*)d_in[1];   // [N, 16, 96]
    const float* target_vels = (const float*)d_in[2];   // [N, 25, 96]
    float* out = (float*)d_out;                          // [25, 96]

    const int N = in_sizes[1] / ROW_F;
    const int blocks = (N + WARPS_PER_BLOCK - 1) / WARPS_PER_BLOCK;

    nn_dist_kernel<<<blocks, 256>>>(in_pose, train_poses, N);

    // Gather with programmatic dependent launch: overlaps launch/prologue
    // with the dist kernel; self-synchronizes via gridDependencySynchronize.
    cudaLaunchAttribute attrs[1];
    attrs[0].id = cudaLaunchAttributeProgrammaticStreamSerialization;
    attrs[0].val.programmaticStreamSerializationAllowed = 1;

    cudaLaunchConfig_t cfg = {};
    cfg.gridDim  = dim3(1, 1, 1);
    cfg.blockDim = dim3(256, 1, 1);
    cfg.dynamicSmemBytes = 0;
    cfg.stream = 0;
    cfg.attrs = attrs;
    cfg.numAttrs = 1;

    cudaLaunchKernelEx(&cfg, nn_gather_kernel, target_vels, out);
}